// round 3
// baseline (speedup 1.0000x reference)
#include <cuda_runtime.h>

#define NN   50000
#define NE   640000
#define NF   128
#define HID  256
#define UF   64

// Scratch (allocation-free: __device__ globals)
__device__ float g_P[NN * HID];     // x @ W1[:128] + b1, per node
__device__ float g_agg[NN * HID];   // scatter-sum of edge messages
__device__ float g_cnt[NN];         // edge counts per destination node
__device__ int   g_is64;            // 1 if index arrays are int64, 0 if int32

// ---------------------------------------------------------------------------
// Zero scratch + detect index dtype (int32 vs int64).
// For int32 data read as int64, value = lo + hi*2^32 with hi = a neighboring
// index (generally nonzero) -> out of [0,NN) -> classified int32.
__global__ void zero_kernel(const void* ei_raw) {
    int idx = blockIdx.x * blockDim.x + threadIdx.x;
    int stride = gridDim.x * blockDim.x;
    for (int i = idx; i < NN * HID; i += stride) g_agg[i] = 0.f;
    for (int i = idx; i < NN; i += stride) g_cnt[i] = 0.f;
    if (blockIdx.x == 0 && threadIdx.x == 0) {
        const long long* p = (const long long*)ei_raw;
        int ok = 1;
        for (int i = 0; i < 1024; i++) {
            long long v = p[i];
            if (v < 0 || v >= NN) { ok = 0; break; }
        }
        g_is64 = ok;
    }
}

__device__ __forceinline__ int load_index(const void* p, long long i) {
    long long v = g_is64 ? ((const long long*)p)[i] : (long long)((const int*)p)[i];
    if (v < 0) v = 0;
    if (v >= NN) v = NN - 1;
    return (int)v;
}

// ---------------------------------------------------------------------------
// 16-deep k-step: 4 rows x 16 cols micro-tile FMA
__device__ __forceinline__ void fma_step4(float a0, float a1, float a2, float a3,
                                          const float* __restrict__ bp,
                                          float acc[4][16]) {
#pragma unroll
    for (int j4 = 0; j4 < 4; j4++) {
        float4 bv = *(const float4*)(bp + 4 * j4);
        float b[4] = {bv.x, bv.y, bv.z, bv.w};
#pragma unroll
        for (int jj = 0; jj < 4; jj++) {
            int j = j4 * 4 + jj;
            acc[0][j] = fmaf(a0, b[jj], acc[0][j]);
            acc[1][j] = fmaf(a1, b[jj], acc[1][j]);
            acc[2][j] = fmaf(a2, b[jj], acc[2][j]);
            acc[3][j] = fmaf(a3, b[jj], acc[3][j]);
        }
    }
}

// ---------------------------------------------------------------------------
// P = x @ W1[0:128,:] + b1   (M=50000, K=128, N=256)
__global__ void p_kernel(const float* __restrict__ x,
                         const float* __restrict__ W1,
                         const float* __restrict__ b1) {
    __shared__ float As[16 * 65];
    __shared__ float Bs[16 * 256];
    const int m0 = blockIdx.x * 64;
    const int tid = threadIdx.x;
    const int cx = tid & 15, ry = tid >> 4;
    const int ry4 = ry * 4, cn = cx * 16;
    const int lr = tid >> 2, kq = (tid & 3) * 4;
    const int bk = tid >> 4, bn = (tid & 15) * 16;

    float acc[4][16];
#pragma unroll
    for (int i = 0; i < 4; i++)
#pragma unroll
        for (int j = 0; j < 16; j++) acc[i][j] = 0.f;

    for (int kb = 0; kb < NF; kb += 16) {
        int gm = m0 + lr;
        float4 av = make_float4(0.f, 0.f, 0.f, 0.f);
        if (gm < NN) av = *(const float4*)&x[gm * NF + kb + kq];
        As[(kq + 0) * 65 + lr] = av.x;
        As[(kq + 1) * 65 + lr] = av.y;
        As[(kq + 2) * 65 + lr] = av.z;
        As[(kq + 3) * 65 + lr] = av.w;
        const float* wsrc = &W1[(kb + bk) * HID + bn];
#pragma unroll
        for (int j4 = 0; j4 < 4; j4++)
            *(float4*)&Bs[bk * 256 + bn + 4 * j4] = *(const float4*)(wsrc + 4 * j4);
        __syncthreads();
#pragma unroll
        for (int k = 0; k < 16; k++) {
            float a0 = As[k * 65 + ry4 + 0];
            float a1 = As[k * 65 + ry4 + 1];
            float a2 = As[k * 65 + ry4 + 2];
            float a3 = As[k * 65 + ry4 + 3];
            fma_step4(a0, a1, a2, a3, &Bs[k * 256 + cn], acc);
        }
        __syncthreads();
    }

    float bb[16];
#pragma unroll
    for (int j4 = 0; j4 < 4; j4++) {
        float4 v = *(const float4*)&b1[cn + 4 * j4];
        bb[j4 * 4 + 0] = v.x; bb[j4 * 4 + 1] = v.y;
        bb[j4 * 4 + 2] = v.z; bb[j4 * 4 + 3] = v.w;
    }
#pragma unroll
    for (int i = 0; i < 4; i++) {
        int m = m0 + ry4 + i;
        if (m < NN) {
            float* dst = &g_P[m * HID + cn];
#pragma unroll
            for (int j = 0; j < 16; j++) dst[j] = acc[i][j] + bb[j];
        }
    }
}

// ---------------------------------------------------------------------------
// Fused edge MLP: g = edge_attr @ W1[128:,:] + P[row];  h = relu(g) @ W2 + b2
// then atomicAdd into g_agg[col], g_cnt[col]
__global__ void edge_kernel(const float* __restrict__ ea,
                            const void* __restrict__ ei,
                            const float* __restrict__ W1,
                            const float* __restrict__ W2,
                            const float* __restrict__ b2) {
    extern __shared__ float sm[];
    float* Hs = sm;                       // 64 * 260
    float* Bs = sm + 64 * 260;            // 16 * 256
    float* As = Bs + 16 * 256;            // 16 * 65
    int*   rs = (int*)(As + 16 * 65);     // 64
    int*   cs = rs + 64;                  // 64

    const int e0 = blockIdx.x * 64;
    const int tid = threadIdx.x;
    if (tid < 64) {
        rs[tid] = load_index(ei, e0 + tid);
        cs[tid] = load_index(ei, (long long)NE + e0 + tid);
    }
    const int cx = tid & 15, ry = tid >> 4;
    const int ry4 = ry * 4, cn = cx * 16;
    const int lr = tid >> 2, kq = (tid & 3) * 4;
    const int bk = tid >> 4, bn = (tid & 15) * 16;
    const float* W1b = W1 + NF * HID;

    float acc[4][16];
#pragma unroll
    for (int i = 0; i < 4; i++)
#pragma unroll
        for (int j = 0; j < 16; j++) acc[i][j] = 0.f;
    __syncthreads();

    // GEMM1: edge_attr(64x128) @ W1b(128x256)
    for (int kb = 0; kb < NF; kb += 16) {
        float4 av = *(const float4*)&ea[(long long)(e0 + lr) * NF + kb + kq];
        As[(kq + 0) * 65 + lr] = av.x;
        As[(kq + 1) * 65 + lr] = av.y;
        As[(kq + 2) * 65 + lr] = av.z;
        As[(kq + 3) * 65 + lr] = av.w;
        const float* wsrc = &W1b[(kb + bk) * HID + bn];
#pragma unroll
        for (int j4 = 0; j4 < 4; j4++)
            *(float4*)&Bs[bk * 256 + bn + 4 * j4] = *(const float4*)(wsrc + 4 * j4);
        __syncthreads();
#pragma unroll
        for (int k = 0; k < 16; k++) {
            float a0 = As[k * 65 + ry4 + 0];
            float a1 = As[k * 65 + ry4 + 1];
            float a2 = As[k * 65 + ry4 + 2];
            float a3 = As[k * 65 + ry4 + 3];
            fma_step4(a0, a1, a2, a3, &Bs[k * 256 + cn], acc);
        }
        __syncthreads();
    }

    // + P[row] (L2-resident gather), relu, stash h in smem
#pragma unroll
    for (int i = 0; i < 4; i++) {
        const float* Pr = &g_P[(long long)rs[ry4 + i] * HID + cn];
        float* hd = &Hs[(ry4 + i) * 260 + cn];
#pragma unroll
        for (int j4 = 0; j4 < 4; j4++) {
            float4 pv = *(const float4*)(Pr + 4 * j4);
            float4 hv;
            hv.x = fmaxf(acc[i][j4 * 4 + 0] + pv.x, 0.f);
            hv.y = fmaxf(acc[i][j4 * 4 + 1] + pv.y, 0.f);
            hv.z = fmaxf(acc[i][j4 * 4 + 2] + pv.z, 0.f);
            hv.w = fmaxf(acc[i][j4 * 4 + 3] + pv.w, 0.f);
            *(float4*)(hd + 4 * j4) = hv;
        }
    }
#pragma unroll
    for (int i = 0; i < 4; i++)
#pragma unroll
        for (int j = 0; j < 16; j++) acc[i][j] = 0.f;
    __syncthreads();

    // GEMM2: h(64x256) @ W2(256x256)
    for (int kb = 0; kb < HID; kb += 16) {
        const float* wsrc = &W2[(kb + bk) * HID + bn];
#pragma unroll
        for (int j4 = 0; j4 < 4; j4++)
            *(float4*)&Bs[bk * 256 + bn + 4 * j4] = *(const float4*)(wsrc + 4 * j4);
        __syncthreads();
#pragma unroll
        for (int k = 0; k < 16; k++) {
            float a0 = Hs[(ry4 + 0) * 260 + kb + k];
            float a1 = Hs[(ry4 + 1) * 260 + kb + k];
            float a2 = Hs[(ry4 + 2) * 260 + kb + k];
            float a3 = Hs[(ry4 + 3) * 260 + kb + k];
            fma_step4(a0, a1, a2, a3, &Bs[k * 256 + cn], acc);
        }
        __syncthreads();
    }

    float bb[16];
#pragma unroll
    for (int j4 = 0; j4 < 4; j4++) {
        float4 v = *(const float4*)&b2[cn + 4 * j4];
        bb[j4 * 4 + 0] = v.x; bb[j4 * 4 + 1] = v.y;
        bb[j4 * 4 + 2] = v.z; bb[j4 * 4 + 3] = v.w;
    }
#pragma unroll
    for (int i = 0; i < 4; i++) {
        float* dst = &g_agg[(long long)cs[ry4 + i] * HID + cn];
#pragma unroll
        for (int j = 0; j < 16; j++) atomicAdd(dst + j, acc[i][j] + bb[j]);
    }
    if (tid < 64) atomicAdd(&g_cnt[cs[tid]], 1.0f);
}

// ---------------------------------------------------------------------------
// Fused node MLP: z=[x || agg/cnt || u[batch]] (448) @W3 +b3, relu, @W4 +b4
__global__ void node_kernel(const float* __restrict__ x,
                            const float* __restrict__ u,
                            const void* __restrict__ batch,
                            const float* __restrict__ W3,
                            const float* __restrict__ b3,
                            const float* __restrict__ W4,
                            const float* __restrict__ b4,
                            float* __restrict__ out) {
    extern __shared__ float sm[];
    float* Ts = sm;                       // 64 * 260
    float* Bs = sm + 64 * 260;            // 16 * 256
    float* As = Bs + 16 * 256;            // 16 * 65
    int*   bt = (int*)(As + 16 * 65);     // 64
    float* rc = (float*)(bt + 64);        // 64

    const int m0 = blockIdx.x * 64;
    const int tid = threadIdx.x;
    if (tid < 64) {
        int n = m0 + tid;
        if (n < NN) {
            int b = load_index(batch, n);
            bt[tid] = (b < 64) ? b : 0;
            rc[tid] = 1.0f / fmaxf(g_cnt[n], 1.0f);
        } else {
            bt[tid] = 0;
            rc[tid] = 0.f;
        }
    }
    __syncthreads();

    const int cx = tid & 15, ry = tid >> 4;
    const int ry4 = ry * 4, cn = cx * 16;
    const int lr = tid >> 2, kq = (tid & 3) * 4;
    const int bk = tid >> 4, bn = (tid & 15) * 16;

    float acc[4][16];
#pragma unroll
    for (int i = 0; i < 4; i++)
#pragma unroll
        for (int j = 0; j < 16; j++) acc[i][j] = 0.f;

    // GEMM1: z(64x448) @ W3(448x256), z assembled on the fly
    for (int kb = 0; kb < NF + HID + UF; kb += 16) {
        int n = m0 + lr;
        int k = kb + kq;
        float4 av = make_float4(0.f, 0.f, 0.f, 0.f);
        if (n < NN) {
            if (k < NF) {
                av = *(const float4*)&x[(long long)n * NF + k];
            } else if (k < NF + HID) {
                av = *(const float4*)&g_agg[(long long)n * HID + (k - NF)];
                float r = rc[lr];
                av.x *= r; av.y *= r; av.z *= r; av.w *= r;
            } else {
                av = *(const float4*)&u[bt[lr] * UF + (k - NF - HID)];
            }
        }
        As[(kq + 0) * 65 + lr] = av.x;
        As[(kq + 1) * 65 + lr] = av.y;
        As[(kq + 2) * 65 + lr] = av.z;
        As[(kq + 3) * 65 + lr] = av.w;
        const float* wsrc = &W3[(kb + bk) * HID + bn];
#pragma unroll
        for (int j4 = 0; j4 < 4; j4++)
            *(float4*)&Bs[bk * 256 + bn + 4 * j4] = *(const float4*)(wsrc + 4 * j4);
        __syncthreads();
#pragma unroll
        for (int k2 = 0; k2 < 16; k2++) {
            float a0 = As[k2 * 65 + ry4 + 0];
            float a1 = As[k2 * 65 + ry4 + 1];
            float a2 = As[k2 * 65 + ry4 + 2];
            float a3 = As[k2 * 65 + ry4 + 3];
            fma_step4(a0, a1, a2, a3, &Bs[k2 * 256 + cn], acc);
        }
        __syncthreads();
    }

    // relu(+b3) -> Ts
    float bb[16];
#pragma unroll
    for (int j4 = 0; j4 < 4; j4++) {
        float4 v = *(const float4*)&b3[cn + 4 * j4];
        bb[j4 * 4 + 0] = v.x; bb[j4 * 4 + 1] = v.y;
        bb[j4 * 4 + 2] = v.z; bb[j4 * 4 + 3] = v.w;
    }
#pragma unroll
    for (int i = 0; i < 4; i++) {
        float* td = &Ts[(ry4 + i) * 260 + cn];
#pragma unroll
        for (int j4 = 0; j4 < 4; j4++) {
            float4 tv;
            tv.x = fmaxf(acc[i][j4 * 4 + 0] + bb[j4 * 4 + 0], 0.f);
            tv.y = fmaxf(acc[i][j4 * 4 + 1] + bb[j4 * 4 + 1], 0.f);
            tv.z = fmaxf(acc[i][j4 * 4 + 2] + bb[j4 * 4 + 2], 0.f);
            tv.w = fmaxf(acc[i][j4 * 4 + 3] + bb[j4 * 4 + 3], 0.f);
            *(float4*)(td + 4 * j4) = tv;
        }
    }
    __syncthreads();

    // GEMM2: t(64x256) @ W4(256x128); remap: 2 rows x 16 cols per thread
    const int cx2 = tid & 7, ry2 = tid >> 3;
    const int cn2 = cx2 * 16, rr = ry2 * 2;
    const int bk2 = tid >> 4, bn2 = (tid & 15) * 8;
    float acc2[2][16];
#pragma unroll
    for (int i = 0; i < 2; i++)
#pragma unroll
        for (int j = 0; j < 16; j++) acc2[i][j] = 0.f;

    for (int kb = 0; kb < HID; kb += 16) {
        const float* wsrc = &W4[(kb + bk2) * NF + bn2];
        *(float4*)&Bs[bk2 * 128 + bn2]     = *(const float4*)wsrc;
        *(float4*)&Bs[bk2 * 128 + bn2 + 4] = *(const float4*)(wsrc + 4);
        __syncthreads();
#pragma unroll
        for (int k = 0; k < 16; k++) {
            float a0 = Ts[(rr + 0) * 260 + kb + k];
            float a1 = Ts[(rr + 1) * 260 + kb + k];
            const float* bp = &Bs[k * 128 + cn2];
#pragma unroll
            for (int j4 = 0; j4 < 4; j4++) {
                float4 bv = *(const float4*)(bp + 4 * j4);
                float b[4] = {bv.x, bv.y, bv.z, bv.w};
#pragma unroll
                for (int jj = 0; jj < 4; jj++) {
                    int j = j4 * 4 + jj;
                    acc2[0][j] = fmaf(a0, b[jj], acc2[0][j]);
                    acc2[1][j] = fmaf(a1, b[jj], acc2[1][j]);
                }
            }
        }
        __syncthreads();
    }

    float b4v[16];
#pragma unroll
    for (int j4 = 0; j4 < 4; j4++) {
        float4 v = *(const float4*)&b4[cn2 + 4 * j4];
        b4v[j4 * 4 + 0] = v.x; b4v[j4 * 4 + 1] = v.y;
        b4v[j4 * 4 + 2] = v.z; b4v[j4 * 4 + 3] = v.w;
    }
#pragma unroll
    for (int i = 0; i < 2; i++) {
        int n = m0 + rr + i;
        if (n < NN) {
            float* dst = &out[(long long)n * NF + cn2];
#pragma unroll
            for (int j = 0; j < 16; j++) dst[j] = acc2[i][j] + b4v[j];
        }
    }
}

// ---------------------------------------------------------------------------
extern "C" void kernel_launch(void* const* d_in, const int* in_sizes, int n_in,
                              void* d_out, int out_size) {
    const float* x     = (const float*)d_in[0];
    const void*  ei    = d_in[1];
    const float* ea    = (const float*)d_in[2];
    const float* u     = (const float*)d_in[3];
    const void*  batch = d_in[4];
    const float* W1    = (const float*)d_in[5];
    const float* b1    = (const float*)d_in[6];
    const float* W2    = (const float*)d_in[7];
    const float* b2    = (const float*)d_in[8];
    const float* W3    = (const float*)d_in[9];
    const float* b3    = (const float*)d_in[10];
    const float* W4    = (const float*)d_in[11];
    const float* b4    = (const float*)d_in[12];
    float* out = (float*)d_out;

    const int EDGE_SMEM = (64 * 260 + 16 * 256 + 16 * 65) * 4 + 128 * 2 * 4;
    const int NODE_SMEM = (64 * 260 + 16 * 256 + 16 * 65) * 4 + 64 * 2 * 4;
    static int attr_done = 0;
    if (!attr_done) {
        cudaFuncSetAttribute(edge_kernel, cudaFuncAttributeMaxDynamicSharedMemorySize, EDGE_SMEM);
        cudaFuncSetAttribute(node_kernel, cudaFuncAttributeMaxDynamicSharedMemorySize, NODE_SMEM);
        attr_done = 1;
    }

    zero_kernel<<<2048, 256>>>(ei);
    p_kernel<<<(NN + 63) / 64, 256>>>(x, W1, b1);
    edge_kernel<<<NE / 64, 256, EDGE_SMEM>>>(ea, ei, W1, W2, b2);
    node_kernel<<<(NN + 63) / 64, 256, NODE_SMEM>>>(x, u, batch, W3, b3, W4, b4, out);
}